// round 7
// baseline (speedup 1.0000x reference)
#include <cuda_runtime.h>
#include <math.h>

#define EPS 1e-8f
#define DIM 256
#define VDIM 64    // DIM/4 float4s per row
#define NBLOCKS 1184   // 148 SMs * 8 resident CTAs (2 waves of 4) — fine-grain balance
#define NTHREADS 256

// Per-block best keys (written unconditionally -> no init kernel needed)
__device__ unsigned long long g_block_best[NBLOCKS];

__device__ __forceinline__ unsigned long long pack_key(float sim, unsigned row) {
    unsigned u = __float_as_uint(sim);
    u = (u & 0x80000000u) ? ~u : (u | 0x80000000u);  // order-preserving map
    return ((unsigned long long)u << 32) | (0xFFFFFFFFu - row);
}

// ---------------------------------------------------------------------------
// Kernel A: warp-per-row similarity + packed argmax, 4 rows per iteration
// (proven R3 mainloop). Raw (unnormalized) query: argmax invariant under the
// positive scale 1/(||q||+eps); decode applies it to the winning score only.
// ---------------------------------------------------------------------------
__global__ void __launch_bounds__(NTHREADS, 4)
sim_argmax_kernel(const float4* __restrict__ emb,
                  const float4* __restrict__ q,
                  int n_rows) {
    __shared__ float4 qs[VDIM];
    if (threadIdx.x < VDIM) qs[threadIdx.x] = q[threadIdx.x];
    __syncthreads();

    const int lane  = threadIdx.x & 31;
    const int warp  = (blockIdx.x * blockDim.x + threadIdx.x) >> 5;
    const int nwarp = (gridDim.x * blockDim.x) >> 5;

    const float4 qa = qs[lane];
    const float4 qb = qs[lane + 32];

    unsigned long long best = 0ULL;

    for (int base = warp; base < n_rows; base += 4 * nwarp) {
        int r0 = base;
        int r1 = base + nwarp;
        int r2 = base + 2 * nwarp;
        int r3 = base + 3 * nwarp;
        bool v1 = (r1 < n_rows), v2 = (r2 < n_rows), v3 = (r3 < n_rows);
        int c1 = v1 ? r1 : r0, c2 = v2 ? r2 : r0, c3 = v3 ? r3 : r0;

        const float4* p0 = emb + (size_t)r0 * VDIM;
        const float4* p1 = emb + (size_t)c1 * VDIM;
        const float4* p2 = emb + (size_t)c2 * VDIM;
        const float4* p3 = emb + (size_t)c3 * VDIM;

        // Front-batched: 8 outstanding LDG.128 per lane
        float4 a0 = __ldcs(p0 + lane);
        float4 b0 = __ldcs(p0 + lane + 32);
        float4 a1 = __ldcs(p1 + lane);
        float4 b1 = __ldcs(p1 + lane + 32);
        float4 a2 = __ldcs(p2 + lane);
        float4 b2 = __ldcs(p2 + lane + 32);
        float4 a3 = __ldcs(p3 + lane);
        float4 b3 = __ldcs(p3 + lane + 32);

        float d0 = a0.x*qa.x + a0.y*qa.y + a0.z*qa.z + a0.w*qa.w
                 + b0.x*qb.x + b0.y*qb.y + b0.z*qb.z + b0.w*qb.w;
        float s0 = a0.x*a0.x + a0.y*a0.y + a0.z*a0.z + a0.w*a0.w
                 + b0.x*b0.x + b0.y*b0.y + b0.z*b0.z + b0.w*b0.w;
        float d1 = a1.x*qa.x + a1.y*qa.y + a1.z*qa.z + a1.w*qa.w
                 + b1.x*qb.x + b1.y*qb.y + b1.z*qb.z + b1.w*qb.w;
        float s1 = a1.x*a1.x + a1.y*a1.y + a1.z*a1.z + a1.w*a1.w
                 + b1.x*b1.x + b1.y*b1.y + b1.z*b1.z + b1.w*b1.w;
        float d2 = a2.x*qa.x + a2.y*qa.y + a2.z*qa.z + a2.w*qa.w
                 + b2.x*qb.x + b2.y*qb.y + b2.z*qb.z + b2.w*qb.w;
        float s2 = a2.x*a2.x + a2.y*a2.y + a2.z*a2.z + a2.w*a2.w
                 + b2.x*b2.x + b2.y*b2.y + b2.z*b2.z + b2.w*b2.w;
        float d3 = a3.x*qa.x + a3.y*qa.y + a3.z*qa.z + a3.w*qa.w
                 + b3.x*qb.x + b3.y*qb.y + b3.z*qb.z + b3.w*qb.w;
        float s3 = a3.x*a3.x + a3.y*a3.y + a3.z*a3.z + a3.w*a3.w
                 + b3.x*b3.x + b3.y*b3.y + b3.z*b3.z + b3.w*b3.w;

        #pragma unroll
        for (int off = 16; off > 0; off >>= 1) {
            d0 += __shfl_down_sync(0xFFFFFFFFu, d0, off);
            s0 += __shfl_down_sync(0xFFFFFFFFu, s0, off);
            d1 += __shfl_down_sync(0xFFFFFFFFu, d1, off);
            s1 += __shfl_down_sync(0xFFFFFFFFu, s1, off);
            d2 += __shfl_down_sync(0xFFFFFFFFu, d2, off);
            s2 += __shfl_down_sync(0xFFFFFFFFu, s2, off);
            d3 += __shfl_down_sync(0xFFFFFFFFu, d3, off);
            s3 += __shfl_down_sync(0xFFFFFFFFu, s3, off);
        }

        if (lane == 0) {
            unsigned long long k;
            k = pack_key(d0 / (sqrtf(s0) + EPS), (unsigned)r0);
            if (k > best) best = k;
            if (v1) {
                k = pack_key(d1 / (sqrtf(s1) + EPS), (unsigned)r1);
                if (k > best) best = k;
            }
            if (v2) {
                k = pack_key(d2 / (sqrtf(s2) + EPS), (unsigned)r2);
                if (k > best) best = k;
            }
            if (v3) {
                k = pack_key(d3 / (sqrtf(s3) + EPS), (unsigned)r3);
                if (k > best) best = k;
            }
        }
    }

    // block reduce (lane 0 of each warp holds its best)
    __shared__ unsigned long long sb[NTHREADS / 32];
    int wib = threadIdx.x >> 5;
    if (lane == 0) sb[wib] = best;
    __syncthreads();
    if (threadIdx.x == 0) {
        unsigned long long m = sb[0];
        #pragma unroll
        for (int i = 1; i < NTHREADS / 32; i++) if (sb[i] > m) m = sb[i];
        g_block_best[blockIdx.x] = m;   // unconditional write: no init needed
    }
}

// ---------------------------------------------------------------------------
// Kernel B (PDL): query norm computed CONCURRENTLY with the main kernel,
// then grid-dependency sync, then reduce per-block keys -> [idx, score].
// ---------------------------------------------------------------------------
__global__ void decode_kernel(const float* __restrict__ q, float* __restrict__ out) {
    __shared__ float red[256];
    __shared__ unsigned long long kred[256];
    int t = threadIdx.x;

    // Phase 1 (overlapped with main kernel): ||q||^2
    float v = q[t];
    red[t] = v * v;
    __syncthreads();
    for (int s = 128; s > 0; s >>= 1) {
        if (t < s) red[t] += red[t + s];
        __syncthreads();
    }

    // Phase 2: wait for the main grid's results
    cudaGridDependencySynchronize();

    unsigned long long m = 0ULL;
    for (int i = t; i < NBLOCKS; i += 256) {
        unsigned long long k = g_block_best[i];
        if (k > m) m = k;
    }
    kred[t] = m;
    __syncthreads();

    for (int s = 128; s > 0; s >>= 1) {
        if (t < s) {
            if (kred[t + s] > kred[t]) kred[t] = kred[t + s];
        }
        __syncthreads();
    }

    if (t == 0) {
        float qscale = 1.0f / (sqrtf(red[0]) + EPS);
        unsigned long long k = kred[0];
        unsigned idx = 0xFFFFFFFFu - (unsigned)(k & 0xFFFFFFFFu);
        unsigned u = (unsigned)(k >> 32);
        unsigned bits = (u & 0x80000000u) ? (u ^ 0x80000000u) : ~u;
        out[0] = (float)idx;
        out[1] = __uint_as_float(bits) * qscale;
    }
}

extern "C" void kernel_launch(void* const* d_in, const int* in_sizes, int n_in,
                              void* d_out, int out_size) {
    const float* q   = (const float*)d_in[0];
    const float* emb = (const float*)d_in[1];
    int n_rows = in_sizes[1] / DIM;

    sim_argmax_kernel<<<NBLOCKS, NTHREADS>>>((const float4*)emb,
                                             (const float4*)q, n_rows);

    // Programmatic dependent launch: decode starts early, overlaps its
    // query-norm phase with the main kernel, then grid-syncs for the slots.
    cudaLaunchAttribute attrs[1];
    attrs[0].id = cudaLaunchAttributeProgrammaticStreamSerialization;
    attrs[0].val.programmaticStreamSerializationAllowed = 1;

    cudaLaunchConfig_t cfg = {};
    cfg.gridDim  = dim3(1, 1, 1);
    cfg.blockDim = dim3(256, 1, 1);
    cfg.dynamicSmemBytes = 0;
    cfg.stream = 0;
    cfg.attrs = attrs;
    cfg.numAttrs = 1;

    cudaLaunchKernelEx(&cfg, decode_kernel, q, (float*)d_out);
}

// round 8
// speedup vs baseline: 1.0282x; 1.0282x over previous
#include <cuda_runtime.h>
#include <math.h>

#define EPS 1e-8f
#define DIM 256
#define VDIM 64   // DIM/4 float4s per row
#define NBLOCKS 592   // R3-proven best grid
#define NTHREADS 512

// Per-block best keys (written unconditionally -> no init kernel needed)
__device__ unsigned long long g_block_best[NBLOCKS];

__device__ __forceinline__ unsigned long long pack_key(float sim, unsigned row) {
    unsigned u = __float_as_uint(sim);
    u = (u & 0x80000000u) ? ~u : (u | 0x80000000u);  // order-preserving map
    return ((unsigned long long)u << 32) | (0xFFFFFFFFu - row);
}

// ---------------------------------------------------------------------------
// Kernel A: warp-per-row similarity + packed argmax, 4 CONTIGUOUS rows per
// warp per iteration (4KB contiguous DRAM read per warp -> page locality).
// Raw (unnormalized) query: argmax invariant under positive scale
// 1/(||q||+eps); decode applies it to the winning score only.
// ---------------------------------------------------------------------------
__global__ void __launch_bounds__(NTHREADS, 2)
sim_argmax_kernel(const float4* __restrict__ emb,
                  const float4* __restrict__ q,
                  int n_rows) {
    __shared__ float4 qs[VDIM];
    if (threadIdx.x < VDIM) qs[threadIdx.x] = q[threadIdx.x];
    __syncthreads();

    const int lane  = threadIdx.x & 31;
    const int warp  = (blockIdx.x * blockDim.x + threadIdx.x) >> 5;
    const int nwarp = (gridDim.x * blockDim.x) >> 5;

    const float4 qa = qs[lane];
    const float4 qb = qs[lane + 32];

    unsigned long long best = 0ULL;

    for (int base = warp * 4; base < n_rows; base += 4 * nwarp) {
        int r0 = base;
        int r1 = base + 1;
        int r2 = base + 2;
        int r3 = base + 3;
        bool v1 = (r1 < n_rows), v2 = (r2 < n_rows), v3 = (r3 < n_rows);
        int c1 = v1 ? r1 : r0, c2 = v2 ? r2 : r0, c3 = v3 ? r3 : r0;

        const float4* p0 = emb + (size_t)r0 * VDIM;
        const float4* p1 = emb + (size_t)c1 * VDIM;
        const float4* p2 = emb + (size_t)c2 * VDIM;
        const float4* p3 = emb + (size_t)c3 * VDIM;

        // Front-batched: 8 outstanding LDG.128 per lane, 4KB contiguous/warp
        float4 a0 = __ldcs(p0 + lane);
        float4 b0 = __ldcs(p0 + lane + 32);
        float4 a1 = __ldcs(p1 + lane);
        float4 b1 = __ldcs(p1 + lane + 32);
        float4 a2 = __ldcs(p2 + lane);
        float4 b2 = __ldcs(p2 + lane + 32);
        float4 a3 = __ldcs(p3 + lane);
        float4 b3 = __ldcs(p3 + lane + 32);

        float d0 = a0.x*qa.x + a0.y*qa.y + a0.z*qa.z + a0.w*qa.w
                 + b0.x*qb.x + b0.y*qb.y + b0.z*qb.z + b0.w*qb.w;
        float s0 = a0.x*a0.x + a0.y*a0.y + a0.z*a0.z + a0.w*a0.w
                 + b0.x*b0.x + b0.y*b0.y + b0.z*b0.z + b0.w*b0.w;
        float d1 = a1.x*qa.x + a1.y*qa.y + a1.z*qa.z + a1.w*qa.w
                 + b1.x*qb.x + b1.y*qb.y + b1.z*qb.z + b1.w*qb.w;
        float s1 = a1.x*a1.x + a1.y*a1.y + a1.z*a1.z + a1.w*a1.w
                 + b1.x*b1.x + b1.y*b1.y + b1.z*b1.z + b1.w*b1.w;
        float d2 = a2.x*qa.x + a2.y*qa.y + a2.z*qa.z + a2.w*qa.w
                 + b2.x*qb.x + b2.y*qb.y + b2.z*qb.z + b2.w*qb.w;
        float s2 = a2.x*a2.x + a2.y*a2.y + a2.z*a2.z + a2.w*a2.w
                 + b2.x*b2.x + b2.y*b2.y + b2.z*b2.z + b2.w*b2.w;
        float d3 = a3.x*qa.x + a3.y*qa.y + a3.z*qa.z + a3.w*qa.w
                 + b3.x*qb.x + b3.y*qb.y + b3.z*qb.z + b3.w*qb.w;
        float s3 = a3.x*a3.x + a3.y*a3.y + a3.z*a3.z + a3.w*a3.w
                 + b3.x*b3.x + b3.y*b3.y + b3.z*b3.z + b3.w*b3.w;

        #pragma unroll
        for (int off = 16; off > 0; off >>= 1) {
            d0 += __shfl_down_sync(0xFFFFFFFFu, d0, off);
            s0 += __shfl_down_sync(0xFFFFFFFFu, s0, off);
            d1 += __shfl_down_sync(0xFFFFFFFFu, d1, off);
            s1 += __shfl_down_sync(0xFFFFFFFFu, s1, off);
            d2 += __shfl_down_sync(0xFFFFFFFFu, d2, off);
            s2 += __shfl_down_sync(0xFFFFFFFFu, s2, off);
            d3 += __shfl_down_sync(0xFFFFFFFFu, d3, off);
            s3 += __shfl_down_sync(0xFFFFFFFFu, s3, off);
        }

        if (lane == 0) {
            unsigned long long k;
            k = pack_key(d0 / (sqrtf(s0) + EPS), (unsigned)r0);
            if (k > best) best = k;
            if (v1) {
                k = pack_key(d1 / (sqrtf(s1) + EPS), (unsigned)r1);
                if (k > best) best = k;
            }
            if (v2) {
                k = pack_key(d2 / (sqrtf(s2) + EPS), (unsigned)r2);
                if (k > best) best = k;
            }
            if (v3) {
                k = pack_key(d3 / (sqrtf(s3) + EPS), (unsigned)r3);
                if (k > best) best = k;
            }
        }
    }

    // block reduce (lane 0 of each warp holds its best)
    __shared__ unsigned long long sb[NTHREADS / 32];
    int wib = threadIdx.x >> 5;
    if (lane == 0) sb[wib] = best;
    __syncthreads();
    if (threadIdx.x == 0) {
        unsigned long long m = sb[0];
        #pragma unroll
        for (int i = 1; i < NTHREADS / 32; i++) if (sb[i] > m) m = sb[i];
        g_block_best[blockIdx.x] = m;   // unconditional write: no init needed
    }
}

// ---------------------------------------------------------------------------
// Kernel B: reduce per-block keys + query norm -> [best_idx, best_score]
// ---------------------------------------------------------------------------
__global__ void decode_kernel(const float* __restrict__ q, float* __restrict__ out) {
    __shared__ float red[256];
    __shared__ unsigned long long kred[256];
    int t = threadIdx.x;

    float v = q[t];
    red[t] = v * v;

    unsigned long long m = 0ULL;
    for (int i = t; i < NBLOCKS; i += 256) {
        unsigned long long k = g_block_best[i];
        if (k > m) m = k;
    }
    kred[t] = m;
    __syncthreads();

    for (int s = 128; s > 0; s >>= 1) {
        if (t < s) {
            red[t] += red[t + s];
            if (kred[t + s] > kred[t]) kred[t] = kred[t + s];
        }
        __syncthreads();
    }

    if (t == 0) {
        float qscale = 1.0f / (sqrtf(red[0]) + EPS);
        unsigned long long k = kred[0];
        unsigned idx = 0xFFFFFFFFu - (unsigned)(k & 0xFFFFFFFFu);
        unsigned u = (unsigned)(k >> 32);
        unsigned bits = (u & 0x80000000u) ? (u ^ 0x80000000u) : ~u;
        out[0] = (float)idx;
        out[1] = __uint_as_float(bits) * qscale;
    }
}

extern "C" void kernel_launch(void* const* d_in, const int* in_sizes, int n_in,
                              void* d_out, int out_size) {
    const float* q   = (const float*)d_in[0];
    const float* emb = (const float*)d_in[1];
    int n_rows = in_sizes[1] / DIM;

    sim_argmax_kernel<<<NBLOCKS, NTHREADS>>>((const float4*)emb,
                                             (const float4*)q, n_rows);
    decode_kernel<<<1, 256>>>(q, (float*)d_out);
}